// round 3
// baseline (speedup 1.0000x reference)
#include <cuda_runtime.h>
#include <cuda_bf16.h>

#define MAXN 8192
__device__ float g_x[MAXN];
__device__ float g_y[MAXN];

#define TPB 128
#define ILP 4
#define JT  128

__global__ void precompute_xy(const float* __restrict__ ell,
                              const float* __restrict__ theta, int N) {
    int i = blockIdx.x * blockDim.x + threadIdx.x;
    if (i < N) {
        float r = expf(ell[i]);
        float sn, cs;
        sincosf(theta[i], &sn, &cs);
        float ax = r * (fabsf(cs) + 1e-10f);
        float ay = r * (fabsf(sn) + 1e-10f);
        g_x[i] = (cs >= 0.f) ? ax : -ax;
        g_y[i] = (sn >= 0.f) ? ay : -ay;
    }
}

__global__ void __launch_bounds__(TPB)
force_kernel(const float* __restrict__ ell, const float* __restrict__ theta,
             const float* __restrict__ s, const unsigned char* __restrict__ frozen,
             float* __restrict__ out, int N)
{
    __shared__ float sx[JT], sy[JT], sl[JT], st[JT], ssv[JT];

    const float CUT2  = 6.854101966249685f;   // phi^4
    const float PI_F  = 3.14159265358979323846f;
    const float TAU_F = 6.28318530717958647692f;

    int tid = threadIdx.x;
    int j = blockIdx.y * JT + tid;            // JT == TPB: one load per thread
    if (j < N) {
        sx[tid] = g_x[j]; sy[tid] = g_y[j];
        sl[tid] = ell[j]; st[tid] = theta[j]; ssv[tid] = s[j];
    } else {
        sx[tid] = 1e30f; sy[tid] = 1e30f;     // never passes cutoff
        sl[tid] = 0.f;   st[tid] = 0.f;  ssv[tid] = 0.f;
    }
    __syncthreads();

    int ibase = blockIdx.x * (TPB * ILP) + tid;

    float xi[ILP], yi[ILP], li[ILP], ti[ILP], si[ILP];
    float fl[ILP], ft[ILP];
#pragma unroll
    for (int k = 0; k < ILP; k++) {
        int i = ibase + k * TPB;
        if (i < N) {
            xi[k] = g_x[i]; yi[k] = g_y[i];
            li[k] = ell[i]; ti[k] = theta[i]; si[k] = s[i];
        } else {
            xi[k] = -1e30f; yi[k] = -1e30f;
            li[k] = 0.f; ti[k] = 0.f; si[k] = 0.f;
        }
        fl[k] = 0.f; ft[k] = 0.f;
    }

#pragma unroll 2
    for (int jj = 0; jj < JT; jj++) {
        float xj = sx[jj], yj = sy[jj];
        float lj = sl[jj], tj = st[jj], sj = ssv[jj];
#pragma unroll
        for (int k = 0; k < ILP; k++) {
            float dx = xj - xi[k];
            float dy = yj - yi[k];
            float d2 = fmaf(dx, dx, dy * dy);
            // d2 > 0 excludes the diagonal exactly (x_i - x_i == 0)
            if (d2 <= CUT2 && d2 > 0.f) {
                float f = si[k] * sj * rsqrtf(d2);
                fl[k] = fmaf(f, lj - li[k], fl[k]);
                float dt = tj - ti[k];
                float dth = (dt >= PI_F)  ? dt - TAU_F
                          : (dt <  -PI_F) ? dt + TAU_F
                          : dt;
                ft[k] = fmaf(f, dth, ft[k]);
            }
        }
    }

#pragma unroll
    for (int k = 0; k < ILP; k++) {
        int i = ibase + k * TPB;
        if (i < N && !frozen[i]) {
            atomicAdd(&out[i],     fl[k]);
            atomicAdd(&out[N + i], ft[k]);
        }
    }
}

extern "C" void kernel_launch(void* const* d_in, const int* in_sizes, int n_in,
                              void* d_out, int out_size) {
    const float*         ell    = (const float*)d_in[0];
    const float*         theta  = (const float*)d_in[1];
    const float*         s      = (const float*)d_in[2];
    const unsigned char* frozen = (const unsigned char*)d_in[3];
    float* out = (float*)d_out;
    int N = in_sizes[0];

    cudaMemsetAsync(d_out, 0, (size_t)2 * N * sizeof(float));

    precompute_xy<<<(N + 255) / 256, 256>>>(ell, theta, N);

    dim3 grid((N + TPB * ILP - 1) / (TPB * ILP), (N + JT - 1) / JT);
    force_kernel<<<grid, TPB>>>(ell, theta, s, frozen, out, N);
}

// round 6
// speedup vs baseline: 1.1934x; 1.1934x over previous
#include <cuda_runtime.h>
#include <cuda_bf16.h>

#define MAXN 8192
__device__ float4 g_pt[MAXN];   // x, y, ell, theta per point

#define TPB 128
#define ILP 4
#define JT  32

__global__ void precompute_xy(const float* __restrict__ ell,
                              const float* __restrict__ theta, int N) {
    int i = blockIdx.x * blockDim.x + threadIdx.x;
    if (i < N) {
        float e = ell[i];
        float t = theta[i];
        float r = expf(e);
        float sn, cs;
        sincosf(t, &sn, &cs);
        float ax = r * (fabsf(cs) + 1e-10f);
        float ay = r * (fabsf(sn) + 1e-10f);
        float4 p;
        p.x = (cs >= 0.f) ? ax : -ax;
        p.y = (sn >= 0.f) ? ay : -ay;
        p.z = e;
        p.w = t;
        g_pt[i] = p;
    }
}

__global__ void __launch_bounds__(TPB)
force_kernel(const float* __restrict__ s, const unsigned char* __restrict__ frozen,
             float* __restrict__ out, int N)
{
    __shared__ float4 sj4[JT];
    __shared__ float  ssv[JT];

    const float CUT2    = 6.854101966249685f;      // phi^4
    const float TAU_F   = 6.28318530717958647692f;
    const float INV_TAU = 0.15915494309189533577f; // 1/tau

    int tid = threadIdx.x;
    if (tid < JT) {
        int j = blockIdx.y * JT + tid;
        if (j < N) {
            sj4[tid] = g_pt[j];
            ssv[tid] = s[j];
        } else {
            sj4[tid] = make_float4(1e30f, 1e30f, 0.f, 0.f);  // never passes cutoff
            ssv[tid] = 0.f;
        }
    }
    __syncthreads();

    int ibase = blockIdx.x * (TPB * ILP) + tid;

    float xi[ILP], yi[ILP], li[ILP], ti[ILP];
    float fl[ILP], ft[ILP];
#pragma unroll
    for (int k = 0; k < ILP; k++) {
        int i = ibase + k * TPB;
        if (i < N) {
            float4 p = g_pt[i];
            xi[k] = p.x; yi[k] = p.y; li[k] = p.z; ti[k] = p.w;
        } else {
            xi[k] = -1e30f; yi[k] = -1e30f; li[k] = 0.f; ti[k] = 0.f;
        }
        fl[k] = 0.f; ft[k] = 0.f;
    }

#pragma unroll 4
    for (int jj = 0; jj < JT; jj++) {
        float4 J = sj4[jj];
        float sj = ssv[jj];
#pragma unroll
        for (int k = 0; k < ILP; k++) {
            float dx = J.x - xi[k];
            float dy = J.y - yi[k];
            float d2 = fmaf(dx, dx, dy * dy);
            // (0, CUT2] band: excludes diagonal (d2==0 exactly) and far pairs
            bool pass = (d2 <= CUT2) && (d2 > 0.f);
            float f = pass ? sj * rsqrtf(d2) : 0.f;
            float dl = J.z - li[k];
            float dt = J.w - ti[k];
            float dth = fmaf(-TAU_F, rintf(dt * INV_TAU), dt);
            fl[k] = fmaf(f, dl, fl[k]);
            ft[k] = fmaf(f, dth, ft[k]);
        }
    }

#pragma unroll
    for (int k = 0; k < ILP; k++) {
        int i = ibase + k * TPB;
        if (i < N) {
            float m = frozen[i] ? 0.f : s[i];   // s_i factored out of inner loop
            if (m != 0.f) {
                atomicAdd(&out[i],     m * fl[k]);
                atomicAdd(&out[N + i], m * ft[k]);
            }
        }
    }
}

extern "C" void kernel_launch(void* const* d_in, const int* in_sizes, int n_in,
                              void* d_out, int out_size) {
    const float*         ell    = (const float*)d_in[0];
    const float*         theta  = (const float*)d_in[1];
    const float*         s      = (const float*)d_in[2];
    const unsigned char* frozen = (const unsigned char*)d_in[3];
    float* out = (float*)d_out;
    int N = in_sizes[0];

    cudaMemsetAsync(d_out, 0, (size_t)2 * N * sizeof(float));

    precompute_xy<<<(N + 255) / 256, 256>>>(ell, theta, N);

    dim3 grid((N + TPB * ILP - 1) / (TPB * ILP), (N + JT - 1) / JT);
    force_kernel<<<grid, TPB>>>(s, frozen, out, N);
}

// round 7
// speedup vs baseline: 2.0670x; 1.7321x over previous
#include <cuda_runtime.h>
#include <cuda_bf16.h>

#define MAXN 8192
__device__ float4 g_pt[MAXN];   // x, y, ell, theta per point

#define TPB 128
#define ILP 4            // i-lanes per thread = 2 packed f32x2 pairs
#define NPK (ILP / 2)
#define JT  16

typedef unsigned long long u64;

#define ADDX2(o,a,b)   asm("add.rn.f32x2 %0,%1,%2;"    : "=l"(o) : "l"(a), "l"(b))
#define MULX2(o,a,b)   asm("mul.rn.f32x2 %0,%1,%2;"    : "=l"(o) : "l"(a), "l"(b))
#define FMAX2(o,a,b,c) asm("fma.rn.f32x2 %0,%1,%2,%3;" : "=l"(o) : "l"(a), "l"(b), "l"(c))
#define UNPK(lo,hi,in) asm("mov.b64 {%0,%1}, %2;" : "=f"(lo), "=f"(hi) : "l"(in))
#define PK(o,lo,hi)    asm("mov.b64 %0, {%1,%2};" : "=l"(o) : "f"(lo), "f"(hi))

__device__ __forceinline__ u64 dup2f(float v) {
    return (u64)__float_as_uint(v) * 0x100000001ull;
}

__global__ void precompute_xy(const float* __restrict__ ell,
                              const float* __restrict__ theta,
                              float* __restrict__ out, int N) {
    int i = blockIdx.x * blockDim.x + threadIdx.x;
    if (i < N) {
        float e = ell[i];
        float t = theta[i];
        float r = expf(e);
        float sn, cs;
        sincosf(t, &sn, &cs);
        float ax = r * (fabsf(cs) + 1e-10f);
        float ay = r * (fabsf(sn) + 1e-10f);
        float4 p;
        p.x = (cs >= 0.f) ? ax : -ax;
        p.y = (sn >= 0.f) ? ay : -ay;
        p.z = e;
        p.w = t;
        g_pt[i] = p;
        out[i]     = 0.f;     // fused output zeroing (replaces memset launch)
        out[N + i] = 0.f;
    }
}

__global__ void __launch_bounds__(TPB)
force_kernel(const float* __restrict__ s, const unsigned char* __restrict__ frozen,
             float* __restrict__ out, int N)
{
    // j-tile, every scalar pre-duplicated {v,v} so LDS.64 -> packed reg, no pack MOVs
    __shared__ u64 sxx[JT], syy[JT], sll[JT], stt[JT], sss[JT];

    const float CUT2 = 6.854101966249685f;       // phi^4

    int tid = threadIdx.x;
    if (tid < JT) {
        int j = blockIdx.y * JT + tid;
        float x = 1e30f, y = 1e30f, l = 0.f, t = 0.f, sv = 0.f;
        if (j < N) {
            float4 p = g_pt[j];
            x = p.x; y = p.y; l = p.z; t = p.w; sv = s[j];
        }
        sxx[tid] = dup2f(x);  syy[tid] = dup2f(y);
        sll[tid] = dup2f(l);  stt[tid] = dup2f(t);
        sss[tid] = dup2f(sv);
    }
    __syncthreads();

    const u64 EPS2   = dup2f(1e-30f);
    const u64 INVT2  = dup2f(0.15915494309189533577f);   //  1/tau
    const u64 NTAU2  = dup2f(-6.28318530717958647692f);  // -tau

    int ibase = blockIdx.x * (TPB * ILP) + tid;

    u64 nx[NPK], ny[NPK], nl[NPK], nt[NPK], fl[NPK], ft[NPK];
#pragma unroll
    for (int p = 0; p < NPK; p++) {
        float vx[2], vy[2], vl[2], vt[2];
#pragma unroll
        for (int h = 0; h < 2; h++) {
            int i = ibase + (2 * p + h) * TPB;
            if (i < N) {
                float4 q = g_pt[i];
                vx[h] = -q.x; vy[h] = -q.y; vl[h] = -q.z; vt[h] = -q.w;
            } else {
                vx[h] = 1e30f; vy[h] = 1e30f; vl[h] = 0.f; vt[h] = 0.f;
            }
        }
        PK(nx[p], vx[0], vx[1]);
        PK(ny[p], vy[0], vy[1]);
        PK(nl[p], vl[0], vl[1]);
        PK(nt[p], vt[0], vt[1]);
        fl[p] = dup2f(0.f);
        ft[p] = dup2f(0.f);
    }

#pragma unroll 4
    for (int jj = 0; jj < JT; jj++) {
        u64 Jx = sxx[jj], Jy = syy[jj], Jl = sll[jj], Jt = stt[jj], Sj = sss[jj];
#pragma unroll
        for (int p = 0; p < NPK; p++) {
            u64 dx, dy, t0, d2, r, f, dl, dt, u, w, dth;
            ADDX2(dx, Jx, nx[p]);
            ADDX2(dy, Jy, ny[p]);
            FMAX2(t0, dy, dy, EPS2);       // +1e-30: diagonal stays finite,
            FMAX2(d2, dx, dx, t0);         // dl==dth==0 there kills its term
            float d2lo, d2hi;
            UNPK(d2lo, d2hi, d2);
            float rlo = (d2lo <= CUT2) ? rsqrtf(d2lo) : 0.f;
            float rhi = (d2hi <= CUT2) ? rsqrtf(d2hi) : 0.f;
            PK(r, rlo, rhi);
            MULX2(f, r, Sj);
            ADDX2(dl, Jl, nl[p]);
            ADDX2(dt, Jt, nt[p]);
            MULX2(u, dt, INVT2);
            float ulo, uhi;
            UNPK(ulo, uhi, u);
            float wlo = rintf(ulo), whi = rintf(uhi);
            PK(w, wlo, whi);
            FMAX2(dth, NTAU2, w, dt);      // dt - tau*rint(dt/tau)
            FMAX2(fl[p], f, dl, fl[p]);
            FMAX2(ft[p], f, dth, ft[p]);
        }
    }

#pragma unroll
    for (int p = 0; p < NPK; p++) {
        float flo, fhi, tlo, thi;
        UNPK(flo, fhi, fl[p]);
        UNPK(tlo, thi, ft[p]);
        float fls[2] = {flo, fhi};
        float fts[2] = {tlo, thi};
#pragma unroll
        for (int h = 0; h < 2; h++) {
            int i = ibase + (2 * p + h) * TPB;
            if (i < N) {
                float m = frozen[i] ? 0.f : s[i];
                if (m != 0.f) {
                    atomicAdd(&out[i],     m * fls[h]);
                    atomicAdd(&out[N + i], m * fts[h]);
                }
            }
        }
    }
}

extern "C" void kernel_launch(void* const* d_in, const int* in_sizes, int n_in,
                              void* d_out, int out_size) {
    const float*         ell    = (const float*)d_in[0];
    const float*         theta  = (const float*)d_in[1];
    const float*         s      = (const float*)d_in[2];
    const unsigned char* frozen = (const unsigned char*)d_in[3];
    float* out = (float*)d_out;
    int N = in_sizes[0];

    precompute_xy<<<(N + 255) / 256, 256>>>(ell, theta, out, N);

    dim3 grid((N + TPB * ILP - 1) / (TPB * ILP), (N + JT - 1) / JT);
    force_kernel<<<grid, TPB>>>(s, frozen, out, N);
}

// round 8
// speedup vs baseline: 2.1929x; 1.0609x over previous
#include <cuda_runtime.h>
#include <cuda_bf16.h>

#define MAXN 8192
__device__ float4 g_pt[MAXN];   // x, y, ell, theta/tau per point

#define TPB 128
#define ILP 4            // i-lanes per thread = 2 packed f32x2 pairs
#define NPK (ILP / 2)
#define JT  32

typedef unsigned long long u64;

#define ADDX2(o,a,b)   asm("add.rn.f32x2 %0,%1,%2;"    : "=l"(o) : "l"(a), "l"(b))
#define MULX2(o,a,b)   asm("mul.rn.f32x2 %0,%1,%2;"    : "=l"(o) : "l"(a), "l"(b))
#define FMAX2(o,a,b,c) asm("fma.rn.f32x2 %0,%1,%2,%3;" : "=l"(o) : "l"(a), "l"(b), "l"(c))
#define UNPK(lo,hi,in) asm("mov.b64 {%0,%1}, %2;" : "=f"(lo), "=f"(hi) : "l"(in))
#define PK(o,lo,hi)    asm("mov.b64 %0, {%1,%2};" : "=l"(o) : "f"(lo), "f"(hi))

__device__ __forceinline__ u64 dup2f(float v) {
    return (u64)__float_as_uint(v) * 0x100000001ull;
}

__global__ void precompute_xy(const float* __restrict__ ell,
                              const float* __restrict__ theta,
                              float* __restrict__ out, int N) {
    const float INV_TAU = 0.15915494309189533577f;
    int i = blockIdx.x * blockDim.x + threadIdx.x;
    if (i < N) {
        float e = ell[i];
        float t = theta[i];
        float r = expf(e);
        float sn, cs;
        sincosf(t, &sn, &cs);
        float ax = r * (fabsf(cs) + 1e-10f);
        float ay = r * (fabsf(sn) + 1e-10f);
        float4 p;
        p.x = (cs >= 0.f) ? ax : -ax;
        p.y = (sn >= 0.f) ? ay : -ay;
        p.z = e;
        p.w = t * INV_TAU;                 // normalized theta
        g_pt[i] = p;
        out[i]     = 0.f;                  // fused output zeroing
        out[N + i] = 0.f;
    }
}

__global__ void __launch_bounds__(TPB)
force_kernel(const float* __restrict__ s, const unsigned char* __restrict__ frozen,
             float* __restrict__ out, int N)
{
    // j-tile, every scalar pre-duplicated {v,v} so LDS.64 -> packed reg
    __shared__ u64 sxx[JT], syy[JT], sll[JT], stt[JT], sss[JT];

    const float CUT2 = 6.854101966249685f;       // phi^4
    const float TAU_F = 6.28318530717958647692f;

    int tid = threadIdx.x;
    int ibase = blockIdx.x * (TPB * ILP) + tid;

    // ---- prefetch i-data first (overlap LDG latency with j-tile fill) ----
    float4 qi[NPK][2];
#pragma unroll
    for (int p = 0; p < NPK; p++)
#pragma unroll
        for (int h = 0; h < 2; h++) {
            int i = ibase + (2 * p + h) * TPB;
            qi[p][h] = (i < N) ? g_pt[i] : make_float4(-1e30f, -1e30f, 0.f, 0.f);
        }

    // ---- j tile ----
    if (tid < JT) {
        int j = blockIdx.y * JT + tid;
        float x = 1e30f, y = 1e30f, l = 0.f, t = 0.f, sv = 0.f;
        if (j < N) {
            float4 p = g_pt[j];
            x = p.x; y = p.y; l = p.z; t = p.w; sv = s[j];
        }
        sxx[tid] = dup2f(x);  syy[tid] = dup2f(y);
        sll[tid] = dup2f(l);  stt[tid] = dup2f(t);
        sss[tid] = dup2f(sv);
    }

    u64 nx[NPK], ny[NPK], nl[NPK], nt[NPK], fl[NPK], ft[NPK];
#pragma unroll
    for (int p = 0; p < NPK; p++) {
        PK(nx[p], -qi[p][0].x, -qi[p][1].x);
        PK(ny[p], -qi[p][0].y, -qi[p][1].y);
        PK(nl[p], -qi[p][0].z, -qi[p][1].z);
        PK(nt[p], -qi[p][0].w, -qi[p][1].w);
        fl[p] = 0ull;
        ft[p] = 0ull;
    }

    __syncthreads();

    const u64 EPS2 = dup2f(1e-30f);
    const u64 NEG1 = dup2f(-1.0f);

#pragma unroll 8
    for (int jj = 0; jj < JT; jj++) {
        u64 Jx = sxx[jj], Jy = syy[jj], Jl = sll[jj], Jt = stt[jj], Sj = sss[jj];
#pragma unroll
        for (int p = 0; p < NPK; p++) {
            u64 dx, dy, t0, d2, r, f, dl, u, w, dthn;
            ADDX2(dx, Jx, nx[p]);
            ADDX2(dy, Jy, ny[p]);
            FMAX2(t0, dy, dy, EPS2);       // +1e-30: diagonal finite; dl==dthn==0 there
            FMAX2(d2, dx, dx, t0);
            float d2lo, d2hi;
            UNPK(d2lo, d2hi, d2);
            float rlo = (d2lo <= CUT2) ? rsqrtf(d2lo) : 0.f;
            float rhi = (d2hi <= CUT2) ? rsqrtf(d2hi) : 0.f;
            PK(r, rlo, rhi);
            MULX2(f, r, Sj);
            ADDX2(dl, Jl, nl[p]);
            ADDX2(u, Jt, nt[p]);           // (theta_j - theta_i)/tau, in (-1,1)
            float ulo, uhi;
            UNPK(ulo, uhi, u);
            float wlo = rintf(ulo), whi = rintf(uhi);
            PK(w, wlo, whi);
            FMAX2(dthn, w, NEG1, u);       // u - rint(u): wrapped dtheta in turn units
            FMAX2(fl[p], f, dl, fl[p]);
            FMAX2(ft[p], f, dthn, ft[p]);
        }
    }

#pragma unroll
    for (int p = 0; p < NPK; p++) {
        float flo, fhi, tlo, thi;
        UNPK(flo, fhi, fl[p]);
        UNPK(tlo, thi, ft[p]);
        float fls[2] = {flo, fhi};
        float fts[2] = {tlo, thi};
#pragma unroll
        for (int h = 0; h < 2; h++) {
            int i = ibase + (2 * p + h) * TPB;
            if (i < N) {
                float m = frozen[i] ? 0.f : s[i];
                if (m != 0.f) {
                    atomicAdd(&out[i],     m * fls[h]);
                    atomicAdd(&out[N + i], (m * TAU_F) * fts[h]);  // turn units -> radians
                }
            }
        }
    }
}

extern "C" void kernel_launch(void* const* d_in, const int* in_sizes, int n_in,
                              void* d_out, int out_size) {
    const float*         ell    = (const float*)d_in[0];
    const float*         theta  = (const float*)d_in[1];
    const float*         s      = (const float*)d_in[2];
    const unsigned char* frozen = (const unsigned char*)d_in[3];
    float* out = (float*)d_out;
    int N = in_sizes[0];

    precompute_xy<<<(N + 255) / 256, 256>>>(ell, theta, out, N);

    dim3 grid((N + TPB * ILP - 1) / (TPB * ILP), (N + JT - 1) / JT);
    force_kernel<<<grid, TPB>>>(s, frozen, out, N);
}